// round 2
// baseline (speedup 1.0000x reference)
#include <cuda_runtime.h>

#define S    32
#define SP   34
#define VOX  (S*S*S)          // 32768
#define NC   16
#define PZ   35               // overlapping z-pair blocks (z0 = 0..34)

// x repacked: [x:34][y:34][z0:35][c:16][zslot:2]  (pair block = 128 B)
__device__ __align__(128) float g_xp2[SP*SP*PZ*NC*2];   // 5.18 MB
// absolute sample positions per (tap, voxel): (px,py,pz,0)
__device__ __align__(16)  float4 g_p[27*VOX];           // 14.2 MB

// float4-unit strides into g_xp2
#define XSTR4 (SP*PZ*NC*2/4)   // 9520
#define YSTR4 (PZ*NC*2/4)      // 280

// ---------------------------------------------------------------------------
// packed f32x2 helpers
// ---------------------------------------------------------------------------
__device__ __forceinline__ unsigned long long pack2(float a, float b) {
    unsigned long long r;
    asm("mov.b64 %0, {%1, %2};" : "=l"(r) : "f"(a), "f"(b));
    return r;
}
__device__ __forceinline__ void unpack2(unsigned long long v, float& a, float& b) {
    asm("mov.b64 {%0, %1}, %2;" : "=f"(a), "=f"(b) : "l"(v));
}
__device__ __forceinline__ unsigned long long fma2(unsigned long long a,
                                                   unsigned long long b,
                                                   unsigned long long c) {
    unsigned long long d;
    asm("fma.rn.f32x2 %0, %1, %2, %3;" : "=l"(d) : "l"(a), "l"(b), "l"(c));
    return d;
}

// ---------------------------------------------------------------------------
// Pre-pass A: pad + transpose x into overlapping z-pair, channels-inner layout
// One thread per pair block (x,y,z0): reads 32 scalars, writes 128 B.
// ---------------------------------------------------------------------------
__global__ void pad_pairs_kernel(const float* __restrict__ x) {
    int sp = blockIdx.x * blockDim.x + threadIdx.x;
    if (sp >= SP*SP*PZ) return;
    int z0 = sp % PZ;
    int t  = sp / PZ;
    int y  = t % SP;
    int xx = t / SP;
    bool inb_xy = (xx >= 1 && xx <= S && y >= 1 && y <= S);
    bool ib0 = inb_xy && (z0 >= 1 && z0 <= S);        // value at z = z0
    bool ib1 = inb_xy && (z0 <= S - 1);               // value at z = z0+1
    int base = (xx-1)*(S*S) + (y-1)*S;                // + (z-1)
    float4* dst = (float4*)(g_xp2 + (size_t)sp * 32);
#pragma unroll
    for (int q = 0; q < 8; q++) {
        int c0 = 2*q, c1 = 2*q + 1;
        float4 v;
        v.x = ib0 ? x[c0*VOX + base + z0 - 1] : 0.f;
        v.y = ib1 ? x[c0*VOX + base + z0    ] : 0.f;
        v.z = ib0 ? x[c1*VOX + base + z0 - 1] : 0.f;
        v.w = ib1 ? x[c1*VOX + base + z0    ] : 0.f;
        dst[q] = v;
    }
}

// ---------------------------------------------------------------------------
// Pre-pass B: build absolute sample positions p = p0 + pn + offset, in
// output-gather order. One thread per (tap, voxel).
// ---------------------------------------------------------------------------
__global__ void build_p_kernel(const float* __restrict__ off) {
    int g = blockIdx.x * 256 + threadIdx.x;
    int v   = g & (VOX - 1);
    int tix = g >> 15;
    if (tix >= 27) return;
    int oh = v >> 10, ow = (v >> 5) & 31, od = v & 31;
    int a  = tix / 9;
    int bb = (tix - 9*a) / 3;
    int cc = tix % 3;
    int aw    = a * 32 + ow;
    int w_src = aw / 3;
    int r1    = aw - 3 * w_src;
    int u     = r1 * 32 + od;
    int d_src = u / 3;
    int j     = u - 3 * d_src;
    int n     = 9*bb + 3*j + cc;
    int vsrc  = (oh * 32 + w_src) * 32 + d_src;
    // base (oh+1, w_src+1, d_src+1) + kernel offset (bb-1, j-1, cc-1)
    float px = (float)(oh    + bb) + off[ n        * VOX + vsrc];
    float py = (float)(w_src + j ) + off[(n + 27) * VOX + vsrc];
    float pz = (float)(d_src + cc) + off[(n + 54) * VOX + vsrc];
    g_p[tix * VOX + v] = make_float4(px, py, pz, 0.f);
}

// ---------------------------------------------------------------------------
// Main kernel: 8 lanes per output voxel, lane owns channels {2cpart, 2cpart+1}.
// CTA = 256 threads = 32 voxels. Grid = 1024.
// ---------------------------------------------------------------------------
__global__ void __launch_bounds__(256)
deform_conv3d_kernel(const float* __restrict__ wgt, float* __restrict__ out)
{
    // weights: ws[abc][ci][co]
    __shared__ __align__(16) float ws[27*16*16];
    int tid = threadIdx.x;
    for (int idx = tid; idx < 27*16*16; idx += 256) {
        int abc = idx >> 8;
        int ci  = (idx >> 4) & 15;
        int co  = idx & 15;
        ws[idx] = wgt[co*432 + ci*27 + abc];
    }
    __syncthreads();

    const int cpart = tid & 7;
    const int v = blockIdx.x * 32 + (tid >> 3);

    unsigned long long acc2[8];
#pragma unroll
    for (int k = 0; k < 8; k++) acc2[k] = 0ull;   // (0.f, 0.f)

    const float4* __restrict__ xp = (const float4*)g_xp2;

    float4 p4 = g_p[v];   // tap 0 prefetched
#pragma unroll 1
    for (int t = 0; t < 27; t++) {
        float4 pn = g_p[min(t + 1, 26) * VOX + v];   // prefetch next tap

        float px = p4.x, py = p4.y, pz = p4.z;
        float fx = floorf(px), fy = floorf(py), fz = floorf(pz);
        int q0x = min(max((int)fx,     0), 33);
        int q1x = min(max((int)fx + 1, 0), 33);
        int q0y = min(max((int)fy,     0), 33);
        int q1y = min(max((int)fy + 1, 0), 33);
        int q0z = min(max((int)fz,     0), 33);
        int q1z = min(max((int)fz + 1, 0), 33);

        // gather the 4 xy-corners (each covers both z corners + 2 channels)
        int Z  = q0z * 8 + cpart;
        int X0 = q0x * XSTR4, X1 = q1x * XSTR4;
        int Y0 = q0y * YSTR4, Y1 = q1y * YSTR4;
        float4 v00 = xp[X0 + Y0 + Z];
        float4 v01 = xp[X0 + Y1 + Z];
        float4 v10 = xp[X1 + Y0 + Z];
        float4 v11 = xp[X1 + Y1 + Z];

        // mask / snap / clamp (exact reference semantics)
        float pxm = (px < 1.f || px > 32.f) ? fx : px;
        float pym = (py < 1.f || py > 32.f) ? fy : py;
        float pzm = (pz < 1.f || pz > 32.f) ? fz : pz;
        pxm = fminf(fmaxf(pxm, 0.f), 33.f);
        pym = fminf(fmaxf(pym, 0.f), 33.f);
        pzm = fminf(fmaxf(pzm, 0.f), 33.f);

        float lx = 1.f + ((float)q0x - pxm);
        float hx = 1.f - ((float)q1x - pxm);
        float ly = 1.f + ((float)q0y - pym);
        float hy = 1.f - ((float)q1y - pym);
        float lz = 1.f + ((float)q0z - pzm);
        float hz = 1.f - ((float)q1z - pzm);

        // z-clamp: both corners collapse onto the low slot
        bool zc   = (q1z == q0z);
        float wlo = zc ? (lz + hz) : lz;
        float whi = zc ? 0.f       : hz;

        // z-combine per channel
        float t00a = fmaf(whi, v00.y, wlo * v00.x);
        float t00b = fmaf(whi, v00.w, wlo * v00.z);
        float t01a = fmaf(whi, v01.y, wlo * v01.x);
        float t01b = fmaf(whi, v01.w, wlo * v01.z);
        float t10a = fmaf(whi, v10.y, wlo * v10.x);
        float t10b = fmaf(whi, v10.w, wlo * v10.z);
        float t11a = fmaf(whi, v11.y, wlo * v11.x);
        float t11b = fmaf(whi, v11.w, wlo * v11.z);

        // xy-combine
        float g00 = lx * ly, g01 = lx * hy, g10 = hx * ly, g11 = hx * hy;
        float s0 = fmaf(g11, t11a, fmaf(g10, t10a, fmaf(g01, t01a, g00 * t00a)));
        float s1 = fmaf(g11, t11b, fmaf(g10, t10b, fmaf(g01, t01b, g00 * t00b)));

        unsigned long long s0p = pack2(s0, s0);
        unsigned long long s1p = pack2(s1, s1);

        // conv accumulate: acc[co] += w[co][ci0]*s0 + w[co][ci1]*s1 (packed co-pairs)
        const ulonglong2* wp = (const ulonglong2*)(ws + t*256 + cpart*32);
#pragma unroll
        for (int r = 0; r < 4; r++) {
            ulonglong2 wa = wp[r];       // ci0, co 4r..4r+3
            ulonglong2 wb = wp[4 + r];   // ci1
            acc2[2*r]     = fma2(wa.x, s0p, acc2[2*r]);
            acc2[2*r + 1] = fma2(wa.y, s0p, acc2[2*r + 1]);
            acc2[2*r]     = fma2(wb.x, s1p, acc2[2*r]);
            acc2[2*r + 1] = fma2(wb.y, s1p, acc2[2*r + 1]);
        }

        p4 = pn;
    }

    // unpack and reduce partial ci sums across the 8 lanes of this voxel
    float accf[16];
#pragma unroll
    for (int k = 0; k < 8; k++) unpack2(acc2[k], accf[2*k], accf[2*k + 1]);
#pragma unroll
    for (int co = 0; co < 16; co++) {
        accf[co] += __shfl_xor_sync(0xffffffffu, accf[co], 1);
        accf[co] += __shfl_xor_sync(0xffffffffu, accf[co], 2);
        accf[co] += __shfl_xor_sync(0xffffffffu, accf[co], 4);
    }
    int co0 = cpart * 2;
    out[ co0      * VOX + v] = accf[co0];
    out[(co0 + 1) * VOX + v] = accf[co0 + 1];
}

// ---------------------------------------------------------------------------
extern "C" void kernel_launch(void* const* d_in, const int* in_sizes, int n_in,
                              void* d_out, int out_size) {
    const float* x   = (const float*)d_in[0];   // [1,16,32,32,32]
    const float* off = (const float*)d_in[1];   // [1,81,32,32,32]
    const float* wgt = (const float*)d_in[2];   // [16,16,3,3,3]
    float* out = (float*)d_out;                 // [1,16,32,32,32]

    pad_pairs_kernel<<<(SP*SP*PZ + 255) / 256, 256>>>(x);
    build_p_kernel<<<(27 * VOX) / 256, 256>>>(off);
    deform_conv3d_kernel<<<VOX / 32, 256>>>(wgt, out);
}

// round 3
// speedup vs baseline: 3.2073x; 3.2073x over previous
#include <cuda_runtime.h>

#define S    32
#define SP   34
#define VOX  (S*S*S)          // 32768
#define NC   16
#define PZ   35               // overlapping z-pair blocks (z0 = 0..34)

// x repacked: [x:34][y:34][z0:35][c:16][zslot:2]  (pair block = 128 B)
__device__ __align__(128) float g_xp2[SP*SP*PZ*NC*2];   // 5.18 MB
// absolute sample positions per (tap, voxel): (px,py,pz,0)
__device__ __align__(16)  float4 g_p[27*VOX];           // 14.2 MB

// float4-unit strides into g_xp2
#define XSTR4 (SP*PZ*NC*2/4)   // 9520
#define YSTR4 (PZ*NC*2/4)      // 280

// ---------------------------------------------------------------------------
// Pre-pass A: pad + transpose x into overlapping z-pair, channels-inner layout.
// One thread per (pair block, channel-quad q): z0-major so the 4 scalar reads
// are coalesced along z. Writes one 16B quarter of the 128B block.
// ---------------------------------------------------------------------------
__global__ void pad_pairs_kernel(const float* __restrict__ x) {
    int g = blockIdx.x * 256 + threadIdx.x;
    if (g >= SP*SP*8*PZ) return;
    int z0 = g % PZ;
    int t  = g / PZ;
    int q  = t & 7;            // channel quad: channels {2q, 2q+1}
    t >>= 3;
    int y  = t % SP;
    int xx = t / SP;
    bool inb_xy = (xx >= 1 && xx <= S && y >= 1 && y <= S);
    bool ib0 = inb_xy && (z0 >= 1 && z0 <= S);        // value at z = z0
    bool ib1 = inb_xy && (z0 <= S - 1);               // value at z = z0+1
    int base = (xx-1)*(S*S) + (y-1)*S;                // + (z-1)
    int c0 = 2*q, c1 = 2*q + 1;
    float4 v;
    v.x = ib0 ? x[c0*VOX + base + z0 - 1] : 0.f;
    v.y = ib1 ? x[c0*VOX + base + z0    ] : 0.f;
    v.z = ib0 ? x[c1*VOX + base + z0 - 1] : 0.f;
    v.w = ib1 ? x[c1*VOX + base + z0    ] : 0.f;
    int sp = (xx*SP + y)*PZ + z0;
    ((float4*)(g_xp2 + (size_t)sp * 32))[q] = v;
}

// ---------------------------------------------------------------------------
// Pre-pass B: absolute sample positions p = p0 + pn + offset, in
// output-gather order. One thread per (tap, voxel).
// ---------------------------------------------------------------------------
__global__ void build_p_kernel(const float* __restrict__ off) {
    int g = blockIdx.x * 256 + threadIdx.x;
    int v   = g & (VOX - 1);
    int tix = g >> 15;
    if (tix >= 27) return;
    int oh = v >> 10, ow = (v >> 5) & 31, od = v & 31;
    int a  = tix / 9;
    int bb = (tix - 9*a) / 3;
    int cc = tix % 3;
    int aw    = a * 32 + ow;
    int w_src = aw / 3;
    int r1    = aw - 3 * w_src;
    int u     = r1 * 32 + od;
    int d_src = u / 3;
    int j     = u - 3 * d_src;
    int n     = 9*bb + 3*j + cc;
    int vsrc  = (oh * 32 + w_src) * 32 + d_src;
    float px = (float)(oh    + bb) + off[ n        * VOX + vsrc];
    float py = (float)(w_src + j ) + off[(n + 27) * VOX + vsrc];
    float pz = (float)(d_src + cc) + off[(n + 54) * VOX + vsrc];
    g_p[tix * VOX + v] = make_float4(px, py, pz, 0.f);
}

// ---------------------------------------------------------------------------
// Main kernel: 8 lanes per output voxel; lane cpart owns channels {2c, 2c+1}
// and both z-corners via the pair layout. CTA = 256 threads = 32 voxels.
// ---------------------------------------------------------------------------
__global__ void __launch_bounds__(256)
deform_conv3d_kernel(const float* __restrict__ wgt, float* __restrict__ out)
{
    // weights: ws[abc][co][ci]  (lane reads float2 at co*64B + cpart*8B: 8
    // distinct 8B addresses over banks 0..15, broadcast x4 -> conflict-free)
    __shared__ __align__(16) float ws[27*16*16];
    int tid = threadIdx.x;
    for (int idx = tid; idx < 27*16*16; idx += 256) {
        int abc = idx >> 8;
        int co  = (idx >> 4) & 15;
        int ci  = idx & 15;
        ws[idx] = wgt[co*432 + ci*27 + abc];
    }
    __syncthreads();

    const int cpart = tid & 7;
    const int v = blockIdx.x * 32 + (tid >> 3);

    float acc[16];
#pragma unroll
    for (int k = 0; k < 16; k++) acc[k] = 0.f;

    const float4* __restrict__ xp = (const float4*)g_xp2;

    float4 p4 = g_p[v];   // tap 0 prefetched
#pragma unroll 1
    for (int t = 0; t < 27; t++) {
        float4 pn = g_p[min(t + 1, 26) * VOX + v];   // prefetch next tap

        float px = p4.x, py = p4.y, pz = p4.z;
        float fx = floorf(px), fy = floorf(py), fz = floorf(pz);
        int q0x = min(max((int)fx,     0), 33);
        int q1x = min(max((int)fx + 1, 0), 33);
        int q0y = min(max((int)fy,     0), 33);
        int q1y = min(max((int)fy + 1, 0), 33);
        int q0z = min(max((int)fz,     0), 33);
        int q1z = min(max((int)fz + 1, 0), 33);

        // 4 xy-corner gathers; each covers both z-corners + this lane's 2 ch
        int Z  = q0z * 8 + cpart;
        int X0 = q0x * XSTR4, X1 = q1x * XSTR4;
        int Y0 = q0y * YSTR4, Y1 = q1y * YSTR4;
        float4 v00 = xp[X0 + Y0 + Z];
        float4 v01 = xp[X0 + Y1 + Z];
        float4 v10 = xp[X1 + Y0 + Z];
        float4 v11 = xp[X1 + Y1 + Z];

        // mask / snap / clamp (exact reference semantics)
        float pxm = (px < 1.f || px > 32.f) ? fx : px;
        float pym = (py < 1.f || py > 32.f) ? fy : py;
        float pzm = (pz < 1.f || pz > 32.f) ? fz : pz;
        pxm = fminf(fmaxf(pxm, 0.f), 33.f);
        pym = fminf(fmaxf(pym, 0.f), 33.f);
        pzm = fminf(fmaxf(pzm, 0.f), 33.f);

        float lx = 1.f + ((float)q0x - pxm);
        float hx = 1.f - ((float)q1x - pxm);
        float ly = 1.f + ((float)q0y - pym);
        float hy = 1.f - ((float)q1y - pym);
        float lz = 1.f + ((float)q0z - pzm);
        float hz = 1.f - ((float)q1z - pzm);

        // z-clamp: both corners collapse onto the low slot
        bool zc   = (q1z == q0z);
        float wlo = zc ? (lz + hz) : lz;
        float whi = zc ? 0.f       : hz;

        // z-combine per channel
        float t00a = fmaf(whi, v00.y, wlo * v00.x);
        float t00b = fmaf(whi, v00.w, wlo * v00.z);
        float t01a = fmaf(whi, v01.y, wlo * v01.x);
        float t01b = fmaf(whi, v01.w, wlo * v01.z);
        float t10a = fmaf(whi, v10.y, wlo * v10.x);
        float t10b = fmaf(whi, v10.w, wlo * v10.z);
        float t11a = fmaf(whi, v11.y, wlo * v11.x);
        float t11b = fmaf(whi, v11.w, wlo * v11.z);

        // xy-combine
        float g00 = lx * ly, g01 = lx * hy, g10 = hx * ly, g11 = hx * hy;
        float s0 = fmaf(g11, t11a, fmaf(g10, t10a, fmaf(g01, t01a, g00 * t00a)));
        float s1 = fmaf(g11, t11b, fmaf(g10, t10b, fmaf(g01, t01b, g00 * t00b)));

        // conv accumulate: acc[co] += w[co][ci0]*s0 + w[co][ci1]*s1
        const float2* wp = (const float2*)(ws + t*256 + cpart*2);
#pragma unroll
        for (int co = 0; co < 16; co++) {
            float2 wv = wp[co * 8];
            acc[co] = fmaf(wv.x, s0, fmaf(wv.y, s1, acc[co]));
        }

        p4 = pn;
    }

    // reduce partial ci sums across the 8 lanes of this voxel
#pragma unroll
    for (int co = 0; co < 16; co++) {
        acc[co] += __shfl_xor_sync(0xffffffffu, acc[co], 1);
        acc[co] += __shfl_xor_sync(0xffffffffu, acc[co], 2);
        acc[co] += __shfl_xor_sync(0xffffffffu, acc[co], 4);
    }
    int co0 = cpart * 2;
    out[ co0      * VOX + v] = acc[co0];
    out[(co0 + 1) * VOX + v] = acc[co0 + 1];
}

// ---------------------------------------------------------------------------
extern "C" void kernel_launch(void* const* d_in, const int* in_sizes, int n_in,
                              void* d_out, int out_size) {
    const float* x   = (const float*)d_in[0];   // [1,16,32,32,32]
    const float* off = (const float*)d_in[1];   // [1,81,32,32,32]
    const float* wgt = (const float*)d_in[2];   // [16,16,3,3,3]
    float* out = (float*)d_out;                 // [1,16,32,32,32]

    pad_pairs_kernel<<<(SP*SP*8*PZ + 255) / 256, 256>>>(x);
    build_p_kernel<<<(27 * VOX) / 256, 256>>>(off);
    deform_conv3d_kernel<<<VOX / 32, 256>>>(wgt, out);
}